// round 1
// baseline (speedup 1.0000x reference)
#include <cuda_runtime.h>
#include <cuda_bf16.h>
#include <math.h>

// ---------------- problem constants ----------------
#define DIM   1024
#define NHEAD 8
#define HD    128
#define FF    4096
#define VOC   2048
#define NLM   15
#define NLAYER 5
#define EPSF  1e-6f

// ---------------- scratch (device globals; no allocation allowed) ----------
__device__ float g_h[2 * DIM];        // hidden state, 2 tokens
__device__ float g_qkv[3 * 2 * DIM];  // q[2][1024], k[2][1024], v[2][1024]
__device__ float g_o[2 * DIM];        // attention output
__device__ float g_gu[2 * 2 * FF];    // gate[2][4096] @0, up[2][4096] @8192

// ---------------- block reduction helper ----------------
__device__ __forceinline__ float block_reduce(float v, float* sbuf) {
    int tid = threadIdx.x;
#pragma unroll
    for (int o = 16; o > 0; o >>= 1) v += __shfl_down_sync(0xffffffffu, v, o);
    if ((tid & 31) == 0) sbuf[tid >> 5] = v;
    __syncthreads();
    int nw = blockDim.x >> 5;
    if (tid < 32) {
        float r = (tid < nw) ? sbuf[tid] : 0.f;
#pragma unroll
        for (int o = 16; o > 0; o >>= 1) r += __shfl_down_sync(0xffffffffu, r, o);
        if (tid == 0) sbuf[0] = r;
    }
    __syncthreads();
    float r = sbuf[0];
    __syncthreads();
    return r;
}

// ---------------- embed: h[0]=past, h[1]=codec_emb[tok] ----------------
__global__ void k_embed(const float* __restrict__ past,
                        const float* __restrict__ emb,
                        const int* __restrict__ tok) {
    int t = tok[0];
    for (int i = threadIdx.x + blockIdx.x * blockDim.x; i < DIM;
         i += blockDim.x * gridDim.x) {
        g_h[i] = past[i];
        g_h[DIM + i] = emb[(size_t)t * DIM + i];
    }
}

// ---------------- fused rmsnorm(ln1) + QKV gemv ----------------
// grid: 3 mats * 32 colblocks = 96 ; block 512 (32 cols x 16 dlanes)
__global__ void __launch_bounds__(512) k_gemv_qkv(
    const float* __restrict__ Wq, const float* __restrict__ Wk,
    const float* __restrict__ Wv, const float* __restrict__ lnw) {
    __shared__ float2 xs[DIM];
    __shared__ float sbuf[16];
    __shared__ float racc[2][16][32];
    int tid = threadIdx.x;
    float s0 = 0.f, s1 = 0.f;
    for (int i = tid; i < DIM; i += 512) {
        float a = g_h[i], b = g_h[DIM + i];
        xs[i] = make_float2(a, b);
        s0 += a * a; s1 += b * b;
    }
    s0 = block_reduce(s0, sbuf);
    s1 = block_reduce(s1, sbuf);
    float r0 = rsqrtf(s0 * (1.f / DIM) + EPSF);
    float r1 = rsqrtf(s1 * (1.f / DIM) + EPSF);
    for (int i = tid; i < DIM; i += 512) {
        float w = lnw[i];
        float2 v = xs[i];
        v.x *= r0 * w; v.y *= r1 * w;
        xs[i] = v;
    }
    __syncthreads();

    int mat = blockIdx.x >> 5;
    int colblk = blockIdx.x & 31;
    const float* W = (mat == 0) ? Wq : (mat == 1 ? Wk : Wv);
    int c = tid & 31, dl = tid >> 5;
    int col = colblk * 32 + c;
    const float* Wp = W + (size_t)dl * DIM + col;
    float a0 = 0.f, a1 = 0.f;
#pragma unroll 16
    for (int d = dl; d < DIM; d += 16) {
        float w = Wp[0]; Wp += 16 * DIM;
        float2 x = xs[d];
        a0 += x.x * w; a1 += x.y * w;
    }
    racc[0][dl][c] = a0;
    racc[1][dl][c] = a1;
    __syncthreads();
    if (tid < 32) {
        float t0 = 0.f, t1 = 0.f;
#pragma unroll
        for (int k = 0; k < 16; k++) { t0 += racc[0][k][tid]; t1 += racc[1][k][tid]; }
        int coln = colblk * 32 + tid;
        g_qkv[mat * 2048 + coln] = t0;
        g_qkv[mat * 2048 + DIM + coln] = t1;
    }
}

// ---------------- attention per head (S=2), writes o + kv cache ----------
// grid: 8 blocks (heads), 128 threads
__global__ void __launch_bounds__(128) k_attn(
    const float* __restrict__ qnw, const float* __restrict__ knw,
    float* __restrict__ kv /* layer base in d_out: k @0, v @2048 */) {
    int h = blockIdx.x, j = threadIdx.x;
    __shared__ float sq[2][HD], sk[2][HD];
    __shared__ float sbuf[4];
    float q[2], k[2], v[2];
#pragma unroll
    for (int t = 0; t < 2; t++) {
        q[t] = g_qkv[t * DIM + h * HD + j];
        k[t] = g_qkv[2048 + t * DIM + h * HD + j];
        v[t] = g_qkv[4096 + t * DIM + h * HD + j];
    }
    float qw = qnw[j], kw = knw[j];
#pragma unroll
    for (int t = 0; t < 2; t++) {
        float ss = block_reduce(q[t] * q[t], sbuf);
        q[t] *= rsqrtf(ss * (1.f / HD) + EPSF) * qw;
        ss = block_reduce(k[t] * k[t], sbuf);
        k[t] *= rsqrtf(ss * (1.f / HD) + EPSF) * kw;
    }
    sq[0][j] = q[0]; sq[1][j] = q[1];
    sk[0][j] = k[0]; sk[1][j] = k[1];
    __syncthreads();
    // RoPE: pos0 identity; pos1 angle = theta^(-2*(j%64)/128)
    int jj = j & 63;
    float ang = expf(-(2.f * (float)jj / 128.f) * 9.210340371976184f); // ln(1e4)
    float cs = cosf(ang), sn = sinf(ang);
    float rotq = (j < 64) ? -sq[1][j + 64] : sq[1][j - 64];
    float rotk = (j < 64) ? -sk[1][j + 64] : sk[1][j - 64];
    float q1 = q[1] * cs + rotq * sn;
    float k1 = k[1] * cs + rotk * sn;
    float q0 = q[0], k0 = k[0];
    (void)q0;
    // KV cache: [2][8][2][128] per layer, k then v
    kv[h * 256 + j]        = k0;
    kv[h * 256 + 128 + j]  = k1;
    kv[2048 + h * 256 + j]       = v[0];
    kv[2048 + h * 256 + 128 + j] = v[1];
    // attention (token0 -> only k0; token1 -> softmax over k0,k1)
    float d10 = block_reduce(q1 * k0, sbuf);
    float d11 = block_reduce(q1 * k1, sbuf);
    const float scale = 0.08838834764831845f; // 1/sqrt(128)
    float s10 = d10 * scale, s11 = d11 * scale;
    float m = fmaxf(s10, s11);
    float e0 = expf(s10 - m), e1 = expf(s11 - m);
    float inv = 1.f / (e0 + e1);
    g_o[h * HD + j] = v[0];
    g_o[DIM + h * HD + j] = (e0 * v[0] + e1 * v[1]) * inv;
}

// ---------------- Wo gemv, atomicAdd residual into h ----------------
// grid: 4 dchunks * 32 colblocks = 128
__global__ void __launch_bounds__(512) k_gemv_wo(const float* __restrict__ Wo) {
    __shared__ float2 xs[256];
    __shared__ float racc[2][16][32];
    int tid = threadIdx.x;
    int dchunk = blockIdx.x >> 5;
    int colblk = blockIdx.x & 31;
    int dbase = dchunk * 256;
    if (tid < 256) xs[tid] = make_float2(g_o[dbase + tid], g_o[DIM + dbase + tid]);
    __syncthreads();
    int c = tid & 31, dl = tid >> 5;
    int col = colblk * 32 + c;
    const float* Wp = Wo + (size_t)(dbase + dl) * DIM + col;
    float a0 = 0.f, a1 = 0.f;
#pragma unroll
    for (int d = dl; d < 256; d += 16) {
        float w = Wp[0]; Wp += 16 * DIM;
        float2 x = xs[d];
        a0 += x.x * w; a1 += x.y * w;
    }
    racc[0][dl][c] = a0;
    racc[1][dl][c] = a1;
    __syncthreads();
    if (tid < 32) {
        float t0 = 0.f, t1 = 0.f;
#pragma unroll
        for (int k = 0; k < 16; k++) { t0 += racc[0][k][tid]; t1 += racc[1][k][tid]; }
        int coln = colblk * 32 + tid;
        atomicAdd(&g_h[coln], t0);
        atomicAdd(&g_h[DIM + coln], t1);
    }
}

// ---------------- fused rmsnorm(ln2) + gate/up gemv ----------------
// grid: 2 mats * 128 colblocks = 256
__global__ void __launch_bounds__(512) k_gemv_gateup(
    const float* __restrict__ Wg, const float* __restrict__ Wu,
    const float* __restrict__ lnw) {
    __shared__ float2 xs[DIM];
    __shared__ float sbuf[16];
    __shared__ float racc[2][16][32];
    int tid = threadIdx.x;
    float s0 = 0.f, s1 = 0.f;
    for (int i = tid; i < DIM; i += 512) {
        float a = g_h[i], b = g_h[DIM + i];
        xs[i] = make_float2(a, b);
        s0 += a * a; s1 += b * b;
    }
    s0 = block_reduce(s0, sbuf);
    s1 = block_reduce(s1, sbuf);
    float r0 = rsqrtf(s0 * (1.f / DIM) + EPSF);
    float r1 = rsqrtf(s1 * (1.f / DIM) + EPSF);
    for (int i = tid; i < DIM; i += 512) {
        float w = lnw[i];
        float2 v = xs[i];
        v.x *= r0 * w; v.y *= r1 * w;
        xs[i] = v;
    }
    __syncthreads();

    int mat = blockIdx.x >> 7;
    int colblk = blockIdx.x & 127;
    const float* W = mat ? Wu : Wg;
    int c = tid & 31, dl = tid >> 5;
    int col = colblk * 32 + c;
    const float* Wp = W + (size_t)dl * FF + col;
    float a0 = 0.f, a1 = 0.f;
#pragma unroll 16
    for (int d = dl; d < DIM; d += 16) {
        float w = Wp[0]; Wp += 16 * FF;
        float2 x = xs[d];
        a0 += x.x * w; a1 += x.y * w;
    }
    racc[0][dl][c] = a0;
    racc[1][dl][c] = a1;
    __syncthreads();
    if (tid < 32) {
        float t0 = 0.f, t1 = 0.f;
#pragma unroll
        for (int k = 0; k < 16; k++) { t0 += racc[0][k][tid]; t1 += racc[1][k][tid]; }
        int coln = colblk * 32 + tid;
        g_gu[mat * 8192 + coln] = t0;
        g_gu[mat * 8192 + FF + coln] = t1;
    }
}

// ---------------- down gemv (silu(g)*u staged in smem), atomicAdd into h --
// grid: 4 dchunks * 32 colblocks = 128
__global__ void __launch_bounds__(512) k_gemv_down(const float* __restrict__ Wd) {
    __shared__ float2 xs[1024];
    __shared__ float racc[2][16][32];
    int tid = threadIdx.x;
    int dchunk = blockIdx.x >> 5;
    int colblk = blockIdx.x & 31;
    int dbase = dchunk * 1024;
    for (int i = tid; i < 1024; i += 512) {
        float gg0 = g_gu[dbase + i];
        float uu0 = g_gu[8192 + dbase + i];
        float gg1 = g_gu[FF + dbase + i];
        float uu1 = g_gu[8192 + FF + dbase + i];
        float a = gg0 / (1.f + expf(-gg0)) * uu0;
        float b = gg1 / (1.f + expf(-gg1)) * uu1;
        xs[i] = make_float2(a, b);
    }
    __syncthreads();
    int c = tid & 31, dl = tid >> 5;
    int col = colblk * 32 + c;
    const float* Wp = Wd + (size_t)(dbase + dl) * DIM + col;
    float a0 = 0.f, a1 = 0.f;
#pragma unroll 16
    for (int d = dl; d < 1024; d += 16) {
        float w = Wp[0]; Wp += 16 * DIM;
        float2 x = xs[d];
        a0 += x.x * w; a1 += x.y * w;
    }
    racc[0][dl][c] = a0;
    racc[1][dl][c] = a1;
    __syncthreads();
    if (tid < 32) {
        float t0 = 0.f, t1 = 0.f;
#pragma unroll
        for (int k = 0; k < 16; k++) { t0 += racc[0][k][tid]; t1 += racc[1][k][tid]; }
        int coln = colblk * 32 + tid;
        atomicAdd(&g_h[coln], t0);
        atomicAdd(&g_h[DIM + coln], t1);
    }
}

// ---------------- lm heads: rmsnorm(final) of token1, 15 gemvs -----------
// grid: 15 mats * 64 colblocks = 960
__global__ void __launch_bounds__(512) k_gemv_lm(
    const float* __restrict__ lm, const float* __restrict__ fnw,
    float* __restrict__ logits) {
    __shared__ float xs[DIM];
    __shared__ float sbuf[16];
    __shared__ float racc[16][32];
    int tid = threadIdx.x;
    float s = 0.f;
    for (int i = tid; i < DIM; i += 512) {
        float v = g_h[DIM + i];
        xs[i] = v;
        s += v * v;
    }
    s = block_reduce(s, sbuf);
    float r = rsqrtf(s * (1.f / DIM) + EPSF);
    for (int i = tid; i < DIM; i += 512) xs[i] *= r * fnw[i];
    __syncthreads();

    int mat = blockIdx.x >> 6;
    int colblk = blockIdx.x & 63;
    const float* W = lm + (size_t)mat * DIM * VOC;
    int c = tid & 31, dl = tid >> 5;
    int col = colblk * 32 + c;
    const float* Wp = W + (size_t)dl * VOC + col;
    float a0 = 0.f;
#pragma unroll 16
    for (int d = dl; d < DIM; d += 16) {
        float w = Wp[0]; Wp += 16 * VOC;
        a0 += xs[d] * w;
    }
    racc[dl][c] = a0;
    __syncthreads();
    if (tid < 32) {
        float t0 = 0.f;
#pragma unroll
        for (int k = 0; k < 16; k++) t0 += racc[k][tid];
        logits[(size_t)mat * VOC + colblk * 32 + tid] = t0;
    }
}

// ---------------- host launcher ----------------
extern "C" void kernel_launch(void* const* d_in, const int* in_sizes, int n_in,
                              void* d_out, int out_size) {
    const float *past, *emb, *Wq, *Wk, *Wv, *Wo, *qn, *kn, *ln1, *ln2, *Wg, *Wu,
        *Wd, *fn, *lm;
    const int* tok;
    if (in_sizes[1] == 1) {
        // setup_inputs dict order
        past = (const float*)d_in[0];
        tok  = (const int*)d_in[1];
        emb  = (const float*)d_in[2];
        Wq = (const float*)d_in[3];  Wk = (const float*)d_in[4];
        Wv = (const float*)d_in[5];  Wo = (const float*)d_in[6];
        qn = (const float*)d_in[7];  kn = (const float*)d_in[8];
        ln1 = (const float*)d_in[9]; ln2 = (const float*)d_in[10];
        Wg = (const float*)d_in[11]; Wu = (const float*)d_in[12];
        Wd = (const float*)d_in[13]; fn = (const float*)d_in[14];
        lm = (const float*)d_in[15];
    } else {
        // reference() argument order (cb0_token last)
        past = (const float*)d_in[0];
        emb  = (const float*)d_in[1];
        Wq = (const float*)d_in[2];  Wk = (const float*)d_in[3];
        Wv = (const float*)d_in[4];  Wo = (const float*)d_in[5];
        qn = (const float*)d_in[6];  kn = (const float*)d_in[7];
        ln1 = (const float*)d_in[8]; ln2 = (const float*)d_in[9];
        Wg = (const float*)d_in[10]; Wu = (const float*)d_in[11];
        Wd = (const float*)d_in[12]; fn = (const float*)d_in[13];
        lm = (const float*)d_in[14];
        tok = (const int*)d_in[15];
    }

    float* out = (float*)d_out;
    float* logits = out;            // [15][2048]
    float* kvc = out + NLM * VOC;   // [10][8][2][128]

    k_embed<<<4, 256>>>(past, emb, tok);

    for (int l = 0; l < NLAYER; l++) {
        size_t offA = (size_t)l * DIM * DIM;       // 1024*1024
        size_t offF = (size_t)l * DIM * FF;        // 1024*4096
        k_gemv_qkv<<<96, 512>>>(Wq + offA, Wk + offA, Wv + offA, ln1 + l * DIM);
        k_attn<<<8, 128>>>(qn + l * HD, kn + l * HD, kvc + (size_t)l * 4096);
        k_gemv_wo<<<128, 512>>>(Wo + offA);
        k_gemv_gateup<<<256, 512>>>(Wg + offF, Wu + offF, ln2 + l * DIM);
        k_gemv_down<<<128, 512>>>(Wd + offF);
    }

    k_gemv_lm<<<960, 512>>>(lm, fn, logits);
    (void)n_in; (void)out_size; (void)in_sizes;
}

// round 2
// speedup vs baseline: 1.3894x; 1.3894x over previous
#include <cuda_runtime.h>
#include <cuda_bf16.h>
#include <math.h>

#define DIM    1024
#define NHEAD  8
#define HD     128
#define FF     4096
#define VOC    2048
#define NLM    15
#define NLAYER 5
#define EPSF   1e-6f

// ---------------- scratch (device globals) ----------------
__device__ float g_h[2 * DIM];     // hidden, 2 tokens
__device__ float g_qkv[6 * DIM];   // q[2][1024] | k[2][1024] | v[2][1024]
__device__ float g_gu[4 * FF];     // gate[2][4096] @0, up[2][4096] @8192

// ---------------- reductions ----------------
__device__ __forceinline__ float wred(float v) {
#pragma unroll
    for (int o = 16; o > 0; o >>= 1) v += __shfl_xor_sync(0xffffffffu, v, o);
    return v;
}

// 256-thread block reduce, result broadcast to all
__device__ __forceinline__ float bred256(float v, float* sbuf) {
    int tid = threadIdx.x;
#pragma unroll
    for (int o = 16; o > 0; o >>= 1) v += __shfl_down_sync(0xffffffffu, v, o);
    if ((tid & 31) == 0) sbuf[tid >> 5] = v;
    __syncthreads();
    if (tid < 32) {
        float r = (tid < 8) ? sbuf[tid] : 0.f;
#pragma unroll
        for (int o = 4; o > 0; o >>= 1) r += __shfl_down_sync(0xffffffffu, r, o);
        if (tid == 0) sbuf[0] = r;
    }
    __syncthreads();
    float r = sbuf[0];
    __syncthreads();
    return r;
}

// ---------------- embed + zero logits/qkv ----------------
__global__ void k_embed(const float* __restrict__ past,
                        const float* __restrict__ emb,
                        const int* __restrict__ tok,
                        float* __restrict__ logits) {
    int t = tok[0];
    int gt = blockIdx.x * blockDim.x + threadIdx.x;
    int stride = gridDim.x * blockDim.x;
    for (int i = gt; i < DIM; i += stride) {
        g_h[i] = past[i];
        g_h[DIM + i] = emb[(size_t)t * DIM + i];
    }
    for (int i = gt; i < 6 * DIM; i += stride) g_qkv[i] = 0.f;
    for (int i = gt; i < NLM * VOC; i += stride) logits[i] = 0.f;
}

// ---------------- QKV: rmsnorm(ln1) fused, split-K atomic ----------------
// grid = 24 colblks (3 mats x 8) x 16 dchunks = 384, block 256
__global__ void __launch_bounds__(256) k_qkv(
    const float* __restrict__ Wq, const float* __restrict__ Wk,
    const float* __restrict__ Wv, const float* __restrict__ lnw) {
    int bx = blockIdx.x;
    int colb = bx % 24, dchunk = bx / 24;
    int mat = colb >> 3;
    int colbase = (colb & 7) * 128;
    int dbase = dchunk * 64;
    const float* W = (mat == 0) ? Wq : (mat == 1 ? Wk : Wv);
    int tid = threadIdx.x;
    int c = tid & 31, dl = tid >> 5;

    const float* Wp = W + (size_t)(dbase + dl) * DIM + colbase + c * 4;
    float4 w[8];
#pragma unroll
    for (int i = 0; i < 8; i++) w[i] = *(const float4*)(Wp + (size_t)i * 8 * DIM);

    __shared__ float sbuf[8];
    __shared__ float2 xs[64];
    float s0 = 0.f, s1 = 0.f;
#pragma unroll
    for (int i = 0; i < 4; i++) {
        int idx = tid + i * 256;
        float a = g_h[idx], b = g_h[DIM + idx];
        s0 += a * a; s1 += b * b;
    }
    s0 = bred256(s0, sbuf);
    s1 = bred256(s1, sbuf);
    float r0 = rsqrtf(s0 * (1.f / DIM) + EPSF);
    float r1 = rsqrtf(s1 * (1.f / DIM) + EPSF);
    if (tid < 64) {
        int idx = dbase + tid;
        float wl = lnw[idx];
        xs[tid] = make_float2(g_h[idx] * r0 * wl, g_h[DIM + idx] * r1 * wl);
    }
    __syncthreads();

    float4 a0 = {0, 0, 0, 0}, a1 = {0, 0, 0, 0};
#pragma unroll
    for (int i = 0; i < 8; i++) {
        float2 x = xs[dl + 8 * i];
        a0.x = fmaf(w[i].x, x.x, a0.x); a0.y = fmaf(w[i].y, x.x, a0.y);
        a0.z = fmaf(w[i].z, x.x, a0.z); a0.w = fmaf(w[i].w, x.x, a0.w);
        a1.x = fmaf(w[i].x, x.y, a1.x); a1.y = fmaf(w[i].y, x.y, a1.y);
        a1.z = fmaf(w[i].z, x.y, a1.z); a1.w = fmaf(w[i].w, x.y, a1.w);
    }
    __shared__ float racc0[8][128], racc1[8][128];
    *(float4*)&racc0[dl][c * 4] = a0;
    *(float4*)&racc1[dl][c * 4] = a1;
    __syncthreads();
    if (tid < 128) {
        float t0 = 0.f, t1 = 0.f;
#pragma unroll
        for (int k = 0; k < 8; k++) { t0 += racc0[k][tid]; t1 += racc1[k][tid]; }
        int col = colbase + tid;
        atomicAdd(&g_qkv[mat * 2048 + col], t0);
        atomicAdd(&g_qkv[mat * 2048 + DIM + col], t1);
    }
}

// ---------------- Wo gemv with fused attention + g_gu zero ----------------
// grid = 8 colblks x 16 dchunks = 128, block 256
__global__ void __launch_bounds__(256) k_wo_attn(
    const float* __restrict__ Wo, const float* __restrict__ qnw,
    const float* __restrict__ knw, float* __restrict__ kv) {
    int bx = blockIdx.x;
    int colb = bx & 7, dchunk = bx >> 3;
    int colbase = colb * 128;
    int dbase = dchunk * 64;
    int hh = dchunk >> 1;       // head
    int tid = threadIdx.x;
    int c = tid & 31, dl = tid >> 5;

    const float* Wp = Wo + (size_t)(dbase + dl) * DIM + colbase + c * 4;
    float4 w[8];
#pragma unroll
    for (int i = 0; i < 8; i++) w[i] = *(const float4*)(Wp + (size_t)i * 8 * DIM);

    // zero g_gu for the upcoming gateup kernel (128 blocks x 256 thr covers 16384)
    {
        int idx = bx * 256 + tid;
        if (idx < 4 * FF) g_gu[idx] = 0.f;
    }

    __shared__ float s_e0, s_e1, s_inv;
    __shared__ float2 xs[64];
    __shared__ float racc0[8][128], racc1[8][128];

    if (tid < 32) {  // warp 0 computes attention scalars for head hh
        int l = tid;
        const float4* q1p = (const float4*)(g_qkv + DIM + hh * HD) + l;
        const float4* k0p = (const float4*)(g_qkv + 2048 + hh * HD) + l;
        const float4* k1p = (const float4*)(g_qkv + 2048 + DIM + hh * HD) + l;
        float4 q1 = *q1p, k0 = *k0p, k1 = *k1p;
        float nq1 = wred(q1.x * q1.x + q1.y * q1.y + q1.z * q1.z + q1.w * q1.w);
        float nk0 = wred(k0.x * k0.x + k0.y * k0.y + k0.z * k0.z + k0.w * k0.w);
        float nk1 = wred(k1.x * k1.x + k1.y * k1.y + k1.z * k1.z + k1.w * k1.w);
        float rq1 = rsqrtf(nq1 * (1.f / HD) + EPSF);
        float rk0 = rsqrtf(nk0 * (1.f / HD) + EPSF);
        float rk1 = rsqrtf(nk1 * (1.f / HD) + EPSF);
        float4 qn4 = ((const float4*)qnw)[l];
        float4 kn4 = ((const float4*)knw)[l];
        q1.x *= rq1 * qn4.x; q1.y *= rq1 * qn4.y; q1.z *= rq1 * qn4.z; q1.w *= rq1 * qn4.w;
        k0.x *= rk0 * kn4.x; k0.y *= rk0 * kn4.y; k0.z *= rk0 * kn4.z; k0.w *= rk0 * kn4.w;
        k1.x *= rk1 * kn4.x; k1.y *= rk1 * kn4.y; k1.z *= rk1 * kn4.z; k1.w *= rk1 * kn4.w;
        // RoPE at pos 1 for q1, k1
        int jb = 4 * (l & 15);
        const float C = 9.210340371976184f / 64.f;  // ln(1e4)/64
        float cs0 = cosf((float)0 * 0.f), sn0;      // placeholders (unused)
        (void)cs0; (void)sn0;
        float ang0 = expf(-(float)(jb + 0) * C);
        float ang1 = expf(-(float)(jb + 1) * C);
        float ang2 = expf(-(float)(jb + 2) * C);
        float ang3 = expf(-(float)(jb + 3) * C);
        float csx = cosf(ang0), snx = sinf(ang0);
        float csy = cosf(ang1), sny = sinf(ang1);
        float csz = cosf(ang2), snz = sinf(ang2);
        float csw = cosf(ang3), snw = sinf(ang3);
        float sgn = (l < 16) ? -1.f : 1.f;
        float4 pq, pk;
        pq.x = __shfl_xor_sync(0xffffffffu, q1.x, 16);
        pq.y = __shfl_xor_sync(0xffffffffu, q1.y, 16);
        pq.z = __shfl_xor_sync(0xffffffffu, q1.z, 16);
        pq.w = __shfl_xor_sync(0xffffffffu, q1.w, 16);
        pk.x = __shfl_xor_sync(0xffffffffu, k1.x, 16);
        pk.y = __shfl_xor_sync(0xffffffffu, k1.y, 16);
        pk.z = __shfl_xor_sync(0xffffffffu, k1.z, 16);
        pk.w = __shfl_xor_sync(0xffffffffu, k1.w, 16);
        q1.x = q1.x * csx + sgn * pq.x * snx;
        q1.y = q1.y * csy + sgn * pq.y * sny;
        q1.z = q1.z * csz + sgn * pq.z * snz;
        q1.w = q1.w * csw + sgn * pq.w * snw;
        k1.x = k1.x * csx + sgn * pk.x * snx;
        k1.y = k1.y * csy + sgn * pk.y * sny;
        k1.z = k1.z * csz + sgn * pk.z * snz;
        k1.w = k1.w * csw + sgn * pk.w * snw;
        // scores
        float d10 = wred(q1.x * k0.x + q1.y * k0.y + q1.z * k0.z + q1.w * k0.w);
        float d11 = wred(q1.x * k1.x + q1.y * k1.y + q1.z * k1.z + q1.w * k1.w);
        const float scale = 0.08838834764831845f;
        float s10 = d10 * scale, s11 = d11 * scale;
        float m = fmaxf(s10, s11);
        float e0 = expf(s10 - m), e1 = expf(s11 - m);
        float inv = 1.f / (e0 + e1);
        if (l == 0) { s_e0 = e0; s_e1 = e1; s_inv = inv; }
        // kv cache write: one block per head does it
        if (colb == 0 && (dchunk & 1) == 0) {
            float4 v0 = ((const float4*)(g_qkv + 4096 + hh * HD))[l];
            float4 v1 = ((const float4*)(g_qkv + 4096 + DIM + hh * HD))[l];
            ((float4*)(kv + hh * 256))[l] = k0;
            ((float4*)(kv + hh * 256 + HD))[l] = k1;
            ((float4*)(kv + 2048 + hh * 256))[l] = v0;
            ((float4*)(kv + 2048 + hh * 256 + HD))[l] = v1;
        }
    }
    __syncthreads();
    if (tid < 64) {
        int dim = dbase + tid;
        float v0 = g_qkv[4096 + dim];
        float v1 = g_qkv[4096 + DIM + dim];
        xs[tid] = make_float2(v0, (s_e0 * v0 + s_e1 * v1) * s_inv);
    }
    __syncthreads();

    float4 a0 = {0, 0, 0, 0}, a1 = {0, 0, 0, 0};
#pragma unroll
    for (int i = 0; i < 8; i++) {
        float2 x = xs[dl + 8 * i];
        a0.x = fmaf(w[i].x, x.x, a0.x); a0.y = fmaf(w[i].y, x.x, a0.y);
        a0.z = fmaf(w[i].z, x.x, a0.z); a0.w = fmaf(w[i].w, x.x, a0.w);
        a1.x = fmaf(w[i].x, x.y, a1.x); a1.y = fmaf(w[i].y, x.y, a1.y);
        a1.z = fmaf(w[i].z, x.y, a1.z); a1.w = fmaf(w[i].w, x.y, a1.w);
    }
    *(float4*)&racc0[dl][c * 4] = a0;
    *(float4*)&racc1[dl][c * 4] = a1;
    __syncthreads();
    if (tid < 128) {
        float t0 = 0.f, t1 = 0.f;
#pragma unroll
        for (int k = 0; k < 8; k++) { t0 += racc0[k][tid]; t1 += racc1[k][tid]; }
        int col = colbase + tid;
        atomicAdd(&g_h[col], t0);
        atomicAdd(&g_h[DIM + col], t1);
    }
}

// ---------------- gate/up: rmsnorm(ln2) fused ----------------
// grid = 64 colblks (2 mats x 32) x 16 dchunks = 1024, block 256
__global__ void __launch_bounds__(256) k_gateup(
    const float* __restrict__ Wg, const float* __restrict__ Wu,
    const float* __restrict__ lnw) {
    int bx = blockIdx.x;
    int colb = bx % 64, dchunk = bx / 64;
    int mat = colb >> 5;
    int colbase = (colb & 31) * 128;
    int dbase = dchunk * 64;
    const float* W = mat ? Wu : Wg;
    int tid = threadIdx.x;
    int c = tid & 31, dl = tid >> 5;

    const float* Wp = W + (size_t)(dbase + dl) * FF + colbase + c * 4;
    float4 w[8];
#pragma unroll
    for (int i = 0; i < 8; i++) w[i] = *(const float4*)(Wp + (size_t)i * 8 * FF);

    __shared__ float sbuf[8];
    __shared__ float2 xs[64];
    float s0 = 0.f, s1 = 0.f;
#pragma unroll
    for (int i = 0; i < 4; i++) {
        int idx = tid + i * 256;
        float a = g_h[idx], b = g_h[DIM + idx];
        s0 += a * a; s1 += b * b;
    }
    s0 = bred256(s0, sbuf);
    s1 = bred256(s1, sbuf);
    float r0 = rsqrtf(s0 * (1.f / DIM) + EPSF);
    float r1 = rsqrtf(s1 * (1.f / DIM) + EPSF);
    if (tid < 64) {
        int idx = dbase + tid;
        float wl = lnw[idx];
        xs[tid] = make_float2(g_h[idx] * r0 * wl, g_h[DIM + idx] * r1 * wl);
    }
    __syncthreads();

    float4 a0 = {0, 0, 0, 0}, a1 = {0, 0, 0, 0};
#pragma unroll
    for (int i = 0; i < 8; i++) {
        float2 x = xs[dl + 8 * i];
        a0.x = fmaf(w[i].x, x.x, a0.x); a0.y = fmaf(w[i].y, x.x, a0.y);
        a0.z = fmaf(w[i].z, x.x, a0.z); a0.w = fmaf(w[i].w, x.x, a0.w);
        a1.x = fmaf(w[i].x, x.y, a1.x); a1.y = fmaf(w[i].y, x.y, a1.y);
        a1.z = fmaf(w[i].z, x.y, a1.z); a1.w = fmaf(w[i].w, x.y, a1.w);
    }
    __shared__ float racc0[8][128], racc1[8][128];
    *(float4*)&racc0[dl][c * 4] = a0;
    *(float4*)&racc1[dl][c * 4] = a1;
    __syncthreads();
    if (tid < 128) {
        float t0 = 0.f, t1 = 0.f;
#pragma unroll
        for (int k = 0; k < 8; k++) { t0 += racc0[k][tid]; t1 += racc1[k][tid]; }
        int col = colbase + tid;
        atomicAdd(&g_gu[mat * 8192 + col], t0);
        atomicAdd(&g_gu[mat * 8192 + FF + col], t1);
    }
}

// ---------------- down: silu(g)*u staged, atomic residual; zero g_qkv ------
// grid = 8 colblks x 64 dchunks = 512, block 256
__global__ void __launch_bounds__(256) k_down(const float* __restrict__ Wd) {
    int bx = blockIdx.x;
    int colb = bx & 7, dchunk = bx >> 3;
    int colbase = colb * 128;
    int dbase = dchunk * 64;
    int tid = threadIdx.x;
    int c = tid & 31, dl = tid >> 5;

    const float* Wp = Wd + (size_t)(dbase + dl) * DIM + colbase + c * 4;
    float4 w[8];
#pragma unroll
    for (int i = 0; i < 8; i++) w[i] = *(const float4*)(Wp + (size_t)i * 8 * DIM);

    // zero g_qkv for next layer (blocks 0..23 cover 6144)
    if (bx < 24) g_qkv[bx * 256 + tid] = 0.f;

    __shared__ float2 xs[64];
    __shared__ float racc0[8][128], racc1[8][128];
    if (tid < 64) {
        int idx = dbase + tid;
        float g0 = g_gu[idx],          g1 = g_gu[FF + idx];
        float u0 = g_gu[8192 + idx],   u1 = g_gu[8192 + FF + idx];
        float a = g0 / (1.f + expf(-g0)) * u0;
        float b = g1 / (1.f + expf(-g1)) * u1;
        xs[tid] = make_float2(a, b);
    }
    __syncthreads();

    float4 a0 = {0, 0, 0, 0}, a1 = {0, 0, 0, 0};
#pragma unroll
    for (int i = 0; i < 8; i++) {
        float2 x = xs[dl + 8 * i];
        a0.x = fmaf(w[i].x, x.x, a0.x); a0.y = fmaf(w[i].y, x.x, a0.y);
        a0.z = fmaf(w[i].z, x.x, a0.z); a0.w = fmaf(w[i].w, x.x, a0.w);
        a1.x = fmaf(w[i].x, x.y, a1.x); a1.y = fmaf(w[i].y, x.y, a1.y);
        a1.z = fmaf(w[i].z, x.y, a1.z); a1.w = fmaf(w[i].w, x.y, a1.w);
    }
    *(float4*)&racc0[dl][c * 4] = a0;
    *(float4*)&racc1[dl][c * 4] = a1;
    __syncthreads();
    if (tid < 128) {
        float t0 = 0.f, t1 = 0.f;
#pragma unroll
        for (int k = 0; k < 8; k++) { t0 += racc0[k][tid]; t1 += racc1[k][tid]; }
        int col = colbase + tid;
        atomicAdd(&g_h[col], t0);
        atomicAdd(&g_h[DIM + col], t1);
    }
}

// ---------------- lm heads: final rmsnorm fused, 15 gemvs ----------------
// grid = 240 colblks (15 x 16) x 16 dchunks = 3840, block 256
__global__ void __launch_bounds__(256) k_lm(
    const float* __restrict__ lm, const float* __restrict__ fnw,
    float* __restrict__ logits) {
    int bx = blockIdx.x;
    int colb = bx % 240, dchunk = bx / 240;
    int mat = colb >> 4;
    int colbase = (colb & 15) * 128;
    int dbase = dchunk * 64;
    int tid = threadIdx.x;
    int c = tid & 31, dl = tid >> 5;

    const float* Wp = lm + (size_t)mat * DIM * VOC +
                      (size_t)(dbase + dl) * VOC + colbase + c * 4;
    float4 w[8];
#pragma unroll
    for (int i = 0; i < 8; i++) w[i] = *(const float4*)(Wp + (size_t)i * 8 * VOC);

    __shared__ float sbuf[8];
    __shared__ float xs[64];
    float s = 0.f;
#pragma unroll
    for (int i = 0; i < 4; i++) {
        float v = g_h[DIM + tid + i * 256];
        s += v * v;
    }
    s = bred256(s, sbuf);
    float r = rsqrtf(s * (1.f / DIM) + EPSF);
    if (tid < 64) {
        int idx = dbase + tid;
        xs[tid] = g_h[DIM + idx] * r * fnw[idx];
    }
    __syncthreads();

    float4 a0 = {0, 0, 0, 0};
#pragma unroll
    for (int i = 0; i < 8; i++) {
        float x = xs[dl + 8 * i];
        a0.x = fmaf(w[i].x, x, a0.x); a0.y = fmaf(w[i].y, x, a0.y);
        a0.z = fmaf(w[i].z, x, a0.z); a0.w = fmaf(w[i].w, x, a0.w);
    }
    __shared__ float racc[8][128];
    *(float4*)&racc[dl][c * 4] = a0;
    __syncthreads();
    if (tid < 128) {
        float t0 = 0.f;
#pragma unroll
        for (int k = 0; k < 8; k++) t0 += racc[k][tid];
        atomicAdd(&logits[(size_t)mat * VOC + colbase + tid], t0);
    }
}

// ---------------- host launcher ----------------
extern "C" void kernel_launch(void* const* d_in, const int* in_sizes, int n_in,
                              void* d_out, int out_size) {
    const float *past, *emb, *Wq, *Wk, *Wv, *Wo, *qn, *kn, *ln1, *ln2, *Wg, *Wu,
        *Wd, *fn, *lm;
    const int* tok;
    if (in_sizes[1] == 1) {
        past = (const float*)d_in[0];
        tok  = (const int*)d_in[1];
        emb  = (const float*)d_in[2];
        Wq = (const float*)d_in[3];  Wk = (const float*)d_in[4];
        Wv = (const float*)d_in[5];  Wo = (const float*)d_in[6];
        qn = (const float*)d_in[7];  kn = (const float*)d_in[8];
        ln1 = (const float*)d_in[9]; ln2 = (const float*)d_in[10];
        Wg = (const float*)d_in[11]; Wu = (const float*)d_in[12];
        Wd = (const float*)d_in[13]; fn = (const float*)d_in[14];
        lm = (const float*)d_in[15];
    } else {
        past = (const float*)d_in[0];
        emb  = (const float*)d_in[1];
        Wq = (const float*)d_in[2];  Wk = (const float*)d_in[3];
        Wv = (const float*)d_in[4];  Wo = (const float*)d_in[5];
        qn = (const float*)d_in[6];  kn = (const float*)d_in[7];
        ln1 = (const float*)d_in[8]; ln2 = (const float*)d_in[9];
        Wg = (const float*)d_in[10]; Wu = (const float*)d_in[11];
        Wd = (const float*)d_in[12]; fn = (const float*)d_in[13];
        lm = (const float*)d_in[14];
        tok = (const int*)d_in[15];
    }

    float* out = (float*)d_out;
    float* logits = out;              // [15][2048]
    float* kvc = out + NLM * VOC;     // [10][8][2][128]

    k_embed<<<32, 256>>>(past, emb, tok, logits);

    for (int l = 0; l < NLAYER; l++) {
        size_t offA = (size_t)l * DIM * DIM;
        size_t offF = (size_t)l * DIM * FF;
        k_qkv<<<384, 256>>>(Wq + offA, Wk + offA, Wv + offA, ln1 + l * DIM);
        k_wo_attn<<<128, 256>>>(Wo + offA, qn + l * HD, kn + l * HD,
                                kvc + (size_t)l * 4096);
        k_gateup<<<1024, 256>>>(Wg + offF, Wu + offF, ln2 + l * DIM);
        k_down<<<512, 256>>>(Wd + offF);
    }

    k_lm<<<3840, 256>>>(lm, fn, logits);
    (void)n_in; (void)out_size;
}